// round 14
// baseline (speedup 1.0000x reference)
#include <cuda_runtime.h>
#include <cstdint>

// LmulLinear: out[m,p] = sum_k bitcast_f32(bits(x[m,k]) + bits(w[p,k]) - OFFSET) + bias[p]
// M=256, K=512, P=512.
//
// R14: single launch. 1024 CTAs x 128 thr (load-balance-optimal grid), BM=BN=32,
//      KSPLIT=8, scalar 2x4 microtile (2.19 issues/MAC). Last-arriving CTA per
//      output block reduces 8 partials (fixed order) + bias -> out. No 2nd kernel.

#define M_DIM 256
#define K_DIM 512
#define P_DIM 512
#define BM 32
#define BN 32
#define KSPLIT 8
#define KG (K_DIM / KSPLIT)        // 64 k per CTA
#define SROW (KG + 4)              // 68 words; conflict-free LDS.128
#define TILE_WORDS (BM * SROW)     // 2176 words per tile
#define NGROUP ((M_DIM / BM) * (P_DIM / BN))   // 128 output blocks

__device__ float g_partial[KSPLIT * M_DIM * P_DIM];   // 4 MB scratch, L2-resident
__device__ int   g_count[NGROUP];                      // zero-init; reset each run

static __device__ __forceinline__ float u2f(uint32_t u) { return __uint_as_float(u); }

__global__ void __launch_bounds__(128)
lmul_fused_kernel(const float* __restrict__ x,
                  const float* __restrict__ w,
                  const float* __restrict__ bias,
                  float* __restrict__ out)
{
    constexpr uint32_t OFFSET = 1064828928u;  // 0x3F780000

    __shared__ uint32_t As[TILE_WORDS];   // [BM][SROW]
    __shared__ uint32_t Bs[TILE_WORDS];   // [BN][SROW], offset-folded
    __shared__ int s_last;

    const int tid = threadIdx.x;
    const int tx  = tid & 7;         // p cols: tx + 8c, c<4
    const int ty  = tid >> 3;        // m rows: ty, ty+16
    const int m0  = blockIdx.y * BM;
    const int p0  = blockIdx.x * BN;
    const int ks  = blockIdx.z;
    const int kbase = ks * KG;
    const int gidx  = blockIdx.y * (P_DIM / BN) + blockIdx.x;

    const uint32_t* __restrict__ xu = reinterpret_cast<const uint32_t*>(x);
    const uint32_t* __restrict__ wu = reinterpret_cast<const uint32_t*>(w);

    // ---- load tiles: 32 rows x 16 uint4 each; 4 uint4/thread/tile ----
    #pragma unroll
    for (int i = 0; i < 4; i++) {
        int idx  = tid + i * 128;       // 0..511
        int row  = idx >> 4;            // 16 uint4 per row
        int col4 = idx & 15;
        uint4 va = *reinterpret_cast<const uint4*>(&xu[(m0 + row) * K_DIM + kbase + col4 * 4]);
        *reinterpret_cast<uint4*>(&As[row * SROW + col4 * 4]) = va;
        uint4 vb = *reinterpret_cast<const uint4*>(&wu[(p0 + row) * K_DIM + kbase + col4 * 4]);
        vb.x -= OFFSET; vb.y -= OFFSET; vb.z -= OFFSET; vb.w -= OFFSET;
        *reinterpret_cast<uint4*>(&Bs[row * SROW + col4 * 4]) = vb;
    }
    __syncthreads();

    // ---- main loop: 2x4 microtile, rows {ty, ty+16}, cols {tx+8c} ----
    const uint32_t* abase = As + ty * SROW;
    const uint32_t* bbase = Bs + tx * SROW;

    float acc[2][4];
    #pragma unroll
    for (int r = 0; r < 2; r++)
        #pragma unroll
        for (int c = 0; c < 4; c++) acc[r][c] = 0.f;

    #pragma unroll 4
    for (int j = 0; j < KG / 4; j++) {
        uint4 a0 = *reinterpret_cast<const uint4*>(abase + 4 * j);
        uint4 a1 = *reinterpret_cast<const uint4*>(abase + 16 * SROW + 4 * j);
        uint4 b[4];
        #pragma unroll
        for (int c = 0; c < 4; c++)
            b[c] = *reinterpret_cast<const uint4*>(bbase + (8 * c) * SROW + 4 * j);

        #pragma unroll
        for (int c = 0; c < 4; c++) {
            acc[0][c] += u2f(a0.x + b[c].x);
            acc[1][c] += u2f(a1.x + b[c].x);
            acc[0][c] += u2f(a0.y + b[c].y);
            acc[1][c] += u2f(a1.y + b[c].y);
            acc[0][c] += u2f(a0.z + b[c].z);
            acc[1][c] += u2f(a1.z + b[c].z);
            acc[0][c] += u2f(a0.w + b[c].w);
            acc[1][c] += u2f(a1.w + b[c].w);
        }
    }

    // ---- publish partials (L2 scratch, skip L1) ----
    {
        float* part = g_partial + ks * (M_DIM * P_DIM);
        #pragma unroll
        for (int r = 0; r < 2; r++) {
            const int m = m0 + ty + 16 * r;
            #pragma unroll
            for (int c = 0; c < 4; c++)
                __stcg(&part[m * P_DIM + p0 + tx + 8 * c], acc[r][c]);
        }
    }
    __syncthreads();   // all CTA stores issued before tid0's release fence

    if (tid == 0) {
        __threadfence();                       // release: publish this CTA's partials
        int old = atomicAdd(&g_count[gidx], 1);
        s_last = (old == KSPLIT - 1);
    }
    __syncthreads();
    if (!s_last) return;
    __threadfence();                           // acquire: see all 8 CTAs' partials

    // ---- last CTA reduces: each thread owns 8 consecutive outputs (2 float4) ----
    const int row     = tid >> 2;              // 0..31
    const int colbase = (tid & 3) * 8;         // 0,8,16,24
    const int off     = (m0 + row) * P_DIM + p0 + colbase;

    float4 s0 = __ldcg(reinterpret_cast<const float4*>(g_partial + off));
    float4 s1 = __ldcg(reinterpret_cast<const float4*>(g_partial + off + 4));
    #pragma unroll
    for (int k = 1; k < KSPLIT; k++) {
        const float* pk = g_partial + k * (M_DIM * P_DIM) + off;
        float4 v0 = __ldcg(reinterpret_cast<const float4*>(pk));
        float4 v1 = __ldcg(reinterpret_cast<const float4*>(pk + 4));
        s0.x += v0.x; s0.y += v0.y; s0.z += v0.z; s0.w += v0.w;
        s1.x += v1.x; s1.y += v1.y; s1.z += v1.z; s1.w += v1.w;
    }
    float4 b0 = *reinterpret_cast<const float4*>(bias + p0 + colbase);
    float4 b1 = *reinterpret_cast<const float4*>(bias + p0 + colbase + 4);
    s0.x += b0.x; s0.y += b0.y; s0.z += b0.z; s0.w += b0.w;
    s1.x += b1.x; s1.y += b1.y; s1.z += b1.z; s1.w += b1.w;

    *reinterpret_cast<float4*>(out + off)     = s0;
    *reinterpret_cast<float4*>(out + off + 4) = s1;

    if (tid == 0) g_count[gidx] = 0;   // reset for next graph replay
}

extern "C" void kernel_launch(void* const* d_in, const int* in_sizes, int n_in,
                              void* d_out, int out_size)
{
    const float* x    = (const float*)d_in[0];   // (256, 512)
    const float* w    = (const float*)d_in[1];   // (512, 512)
    const float* bias = (const float*)d_in[2];   // (512,)
    float* out = (float*)d_out;                  // (256, 512)

    dim3 grid(P_DIM / BN, M_DIM / BM, KSPLIT);   // (16, 8, 8) = 1024 CTAs
    lmul_fused_kernel<<<grid, 128>>>(x, w, bias, out);
}